// round 7
// baseline (speedup 1.0000x reference)
#include <cuda_runtime.h>
#include <cuda_fp16.h>

#define BB 256
#define SS 2048
#define EE 64
#define HH 128
#define G4 512   // 4*H

// x_proj scratch: [S][B][4H] fp32 = 1.07 GB
__device__ float g_xp[(size_t)SS * BB * G4];

__device__ __forceinline__ float sigm_f(float x) {
    return 1.0f / (1.0f + __expf(-x));
}
__device__ __forceinline__ float tanh_f(float x) {
    return 2.0f / (1.0f + __expf(-2.0f * x)) - 1.0f;
}

// ---- f32x2 packed-math helpers (sm_103a) ------------------------------------
typedef unsigned long long ull;

__device__ __forceinline__ ull fma2(ull a, ull b, ull c) {
    ull d;
    asm("fma.rn.f32x2 %0, %1, %2, %3;" : "=l"(d) : "l"(a), "l"(b), "l"(c));
    return d;
}
// bf16x2 (lo half = w_k, hi half = w_{k+1}) -> f32x2 (w_k, w_{k+1})
__device__ __forceinline__ ull bf2f2(unsigned int w) {
    unsigned int lo = w << 16;
    unsigned int hi = w & 0xFFFF0000u;
    ull r;
    asm("mov.b64 %0, {%1, %2};" : "=l"(r) : "r"(lo), "r"(hi));
    return r;
}
__device__ __forceinline__ float hsum2(ull v) {
    float x, y;
    asm("mov.b64 {%0, %1}, %2;" : "=f"(x), "=f"(y) : "l"(v));
    return x + y;
}
__device__ __forceinline__ unsigned int f2bf2(float hi, float lo) {
    unsigned int r;
    asm("cvt.rn.satfinite.bf16x2.f32 %0, %1, %2;" : "=r"(r) : "f"(hi), "f"(lo));
    return r;
}
__device__ __forceinline__ ull dup2(float x) {
    ull r;
    asm("mov.b64 %0, {%1, %1};" : "=l"(r) : "f"(x));
    return r;
}

// ---------------------------------------------------------------------------
// Kernel 1: x_proj[s][b][f] = dot(inputs[b][s][:], U_all[f][:]) + b_u[f]
// 8 timesteps per CTA: U tile loaded once, reused across s.
// grid (8 f, 4 b, 256 s-blocks), 256 threads.
// ---------------------------------------------------------------------------
__global__ __launch_bounds__(256) void xproj_kernel(
    const float* __restrict__ inputs,   // [B][S][E]
    const float* __restrict__ U_all,    // [4H][E]
    const float* __restrict__ b_u)      // [4H]
{
    __shared__ float xT[64 * 68];  // [e][b]
    __shared__ float uT[64 * 68];  // [e][f]

    const int s0     = blockIdx.z * 8;
    const int b_base = blockIdx.y * 64;
    const int f_base = blockIdx.x * 64;
    const int tid    = threadIdx.x;
    const int e      = tid & 63;
    const int r0     = tid >> 6;

    // U tile: load once
    #pragma unroll
    for (int i = 0; i < 16; i++) {
        int r = r0 + i * 4;
        uT[e * 68 + r] = U_all[(size_t)(f_base + r) * EE + e];
    }

    const int bi = (tid >> 4) * 4;
    const int fi = (tid & 15) * 4;
    float4 bu = *reinterpret_cast<const float4*>(&b_u[f_base + fi]);

    for (int si = 0; si < 8; si++) {
        const int s = s0 + si;
        __syncthreads();   // protect xT reuse (and first-iter uT visibility)
        #pragma unroll
        for (int i = 0; i < 16; i++) {
            int r = r0 + i * 4;
            xT[e * 68 + r] = inputs[((size_t)(b_base + r) * SS + s) * EE + e];
        }
        __syncthreads();

        ull acc[4][2];
        #pragma unroll
        for (int i = 0; i < 4; i++) { acc[i][0] = 0ULL; acc[i][1] = 0ULL; }

        #pragma unroll 16
        for (int k = 0; k < 64; k++) {
            float4 xv = *reinterpret_cast<const float4*>(&xT[k * 68 + bi]);
            ulonglong2 uvp = *reinterpret_cast<const ulonglong2*>(&uT[k * 68 + fi]);
            float xa[4] = {xv.x, xv.y, xv.z, xv.w};
            #pragma unroll
            for (int i = 0; i < 4; i++) {
                ull xx = dup2(xa[i]);
                acc[i][0] = fma2(xx, uvp.x, acc[i][0]);
                acc[i][1] = fma2(xx, uvp.y, acc[i][1]);
            }
        }

        #pragma unroll
        for (int i = 0; i < 4; i++) {
            size_t o = ((size_t)s * BB + (size_t)(b_base + bi + i)) * G4 + f_base + fi;
            float a0, a1, a2, a3;
            asm("mov.b64 {%0, %1}, %2;" : "=f"(a0), "=f"(a1) : "l"(acc[i][0]));
            asm("mov.b64 {%0, %1}, %2;" : "=f"(a2), "=f"(a3) : "l"(acc[i][1]));
            float4 v;
            v.x = a0 + bu.x;
            v.y = a1 + bu.y;
            v.z = a2 + bu.z;
            v.w = a3 + bu.w;
            *reinterpret_cast<float4*>(&g_xp[o]) = v;
        }
    }
}

// ---------------------------------------------------------------------------
// Kernel 2: scan. 128 CTAs x 1024 threads (8 warps/SMSP), 2 batch rows/CTA.
// thread t: gp = t&1 (gate pair & wd-row), ci = (t>>1)&127, kq = t>>8.
//   gates {2gp, 2gp+1} of column ci: k-quarter kq, BOTH rows (4 f32x2 accs)
//   wd column ci, row gp, k-quarter kq (1 f32x2 acc)
// SMEM reduction over kq (R3-style), 2 barriers/step. Double-buffered h/c.
// Layouts (phase-bank verified conflict-free):
//   wgA : uint4[q=8][t=1024] owner-thread-major (lane-consecutive)
//   wdA : per-(kq,ci) record of 16 words, stride 20 (banks 20c mod 32 distinct
//         within each 8-lane phase)
//   h/c : [buf][row][128] floats — warp-uniform broadcast reads
// ---------------------------------------------------------------------------
#define SM_WG     0                      // 32768 words = 131072 B
#define SM_WD     131072                 // 4*128*20 w  =  40960 B
#define SM_H      172032                 // 512 floats  =   2048 B
#define SM_C      174080                 // 512 floats  =   2048 B
#define SM_PRE    176128                 // 4096 floats =  16384 B
#define SM_CP     192512                 // 1024 floats =   4096 B
#define SM_RED    196608                 // 256 floats  =   1024 B
#define SMEM_BYTES 197632

__global__ __launch_bounds__(1024, 1) void scan_kernel(
    const float* __restrict__ TI,      // [B][S]
    const float* __restrict__ W_all,   // [4H][H]
    const float* __restrict__ b_all,   // [4H]
    const float* __restrict__ W_d,     // [H][H]
    const float* __restrict__ b_d,     // [H]
    const float* __restrict__ W_out,   // [1][H]
    const float* __restrict__ b_out,   // [1]
    float* __restrict__ out)           // [B]
{
    extern __shared__ char smem[];
    unsigned int* wgA = reinterpret_cast<unsigned int*>(smem + SM_WG);
    unsigned int* wdA = reinterpret_cast<unsigned int*>(smem + SM_WD);
    float* hb   = reinterpret_cast<float*>(smem + SM_H);    // [buf][row][128]
    float* cbuf = reinterpret_cast<float*>(smem + SM_C);
    float* preP = reinterpret_cast<float*>(smem + SM_PRE);  // [kq][g][r][128]
    float* cpP  = reinterpret_cast<float*>(smem + SM_CP);   // [kq][gp][128]
    float* red  = reinterpret_cast<float*>(smem + SM_RED);

    const int t  = threadIdx.x;
    const int b0 = blockIdx.x * 2;
    const int gp = t & 1;
    const int ci = (t >> 1) & 127;
    const int kq = t >> 8;

    // ---- one-time packing ----
    // gate weights, owner-thread-major uint4s
    for (int u = t; u < 32768; u += 1024) {
        int wsel = u & 3;
        int e2 = u >> 2;
        int tt = e2 & 1023;
        int q  = e2 >> 10;
        int gpp = tt & 1, cc = (tt >> 1) & 127, kqq = tt >> 8;
        int g  = 2 * gpp + (wsel & 1);
        int kp = kqq * 16 + 2 * q + (wsel >> 1);
        float2 wv = *reinterpret_cast<const float2*>(&W_all[(size_t)(g * 128 + cc) * HH + 2 * kp]);
        wgA[u] = f2bf2(wv.y, wv.x);
    }
    // wd weights: record stride 20 words
    for (int u = t; u < 8192; u += 1024) {
        int p = u & 15, cc = (u >> 4) & 127, kqq = u >> 11;
        int kp = kqq * 16 + p;
        float2 wv = *reinterpret_cast<const float2*>(&W_d[(size_t)cc * HH + 2 * kp]);
        wdA[(kqq * 128 + cc) * 20 + p] = f2bf2(wv.y, wv.x);
    }
    // zero both h/c buffers
    if (t < 512) { hb[t] = 0.0f; cbuf[t] = 0.0f; }

    // gating-thread constants (t < 256: m = gp, col = ci)
    float ba_r[4] = {0, 0, 0, 0}, bd_r = 0.0f, wout_r = 0.0f;
    if (t < 256) {
        #pragma unroll
        for (int g = 0; g < 4; g++) ba_r[g] = b_all[g * 128 + ci];
        bd_r = b_d[ci];
        wout_r = W_out[ci];
    }
    const float bo = b_out[0];

    __syncthreads();

    const uint4* wga  = reinterpret_cast<const uint4*>(wgA) + t;                    // [q*1024]
    const uint4* wda4 = reinterpret_cast<const uint4*>(wdA + (kq * 128 + ci) * 20); // [q2]

    float out_acc = 0.0f;
    float c_reg = 0.0f;   // carried cell state for gating thread (m=gp, ci)

    for (int s = 0; s < SS; s++) {
        const int rb = s & 1;
        const int wb = rb ^ 1;

        // prefetch gating-thread globals (consumed after barrier 1)
        float xpv[4] = {0, 0, 0, 0}, ti = 0.0f;
        if (t < 256) {
            size_t xb = ((size_t)s * BB + b0 + gp) * G4 + ci;
            #pragma unroll
            for (int g = 0; g < 4; g++) xpv[g] = g_xp[xb + g * 128];
            ti = TI[(size_t)(b0 + gp) * SS + s];
        }

        const ulonglong2* h0p = reinterpret_cast<const ulonglong2*>(hb + rb * 256 + kq * 32);
        const ulonglong2* h1p = reinterpret_cast<const ulonglong2*>(hb + rb * 256 + 128 + kq * 32);
        const ulonglong2* cp  = reinterpret_cast<const ulonglong2*>(cbuf + rb * 256 + gp * 128 + kq * 32);

        // ---- Phase A: gate quarter-dots (2 gates x 2 rows) ----
        ull a00 = 0ULL, a01 = 0ULL, a10 = 0ULL, a11 = 0ULL;  // [gl][row]
        #pragma unroll
        for (int q = 0; q < 8; q++) {
            uint4 wv = wga[q * 1024];
            ulonglong2 hh0 = h0p[q];
            ulonglong2 hh1 = h1p[q];
            ull wA0 = bf2f2(wv.x);   // gl=0, k-pair 2q
            ull wB0 = bf2f2(wv.y);   // gl=1, k-pair 2q
            ull wA1 = bf2f2(wv.z);   // gl=0, k-pair 2q+1
            ull wB1 = bf2f2(wv.w);   // gl=1, k-pair 2q+1
            a00 = fma2(hh0.x, wA0, a00); a00 = fma2(hh0.y, wA1, a00);
            a01 = fma2(hh1.x, wA0, a01); a01 = fma2(hh1.y, wA1, a01);
            a10 = fma2(hh0.x, wB0, a10); a10 = fma2(hh0.y, wB1, a10);
            a11 = fma2(hh1.x, wB0, a11); a11 = fma2(hh1.y, wB1, a11);
        }

        // ---- wd quarter-dot (row gp) ----
        ull dac = 0ULL;
        #pragma unroll
        for (int q2 = 0; q2 < 4; q2++) {
            uint4 wv = wda4[q2];
            ulonglong2 ca = cp[2 * q2];
            ulonglong2 cb2 = cp[2 * q2 + 1];
            dac = fma2(ca.x,  bf2f2(wv.x), dac);
            dac = fma2(ca.y,  bf2f2(wv.y), dac);
            dac = fma2(cb2.x, bf2f2(wv.z), dac);
            dac = fma2(cb2.y, bf2f2(wv.w), dac);
        }

        // ---- partial stores ----
        {
            const int gA = 2 * gp, gB = 2 * gp + 1;
            preP[((kq * 4 + gA) * 2 + 0) * 128 + ci] = hsum2(a00);
            preP[((kq * 4 + gA) * 2 + 1) * 128 + ci] = hsum2(a01);
            preP[((kq * 4 + gB) * 2 + 0) * 128 + ci] = hsum2(a10);
            preP[((kq * 4 + gB) * 2 + 1) * 128 + ci] = hsum2(a11);
            cpP[(kq * 2 + gp) * 128 + ci] = hsum2(dac);
        }
        __syncthreads();

        // ---- Phase B: gating (threads 0..255; m = gp, col = ci) ----
        if (t < 256) {
            const int m = gp;
            float pg[4];
            #pragma unroll
            for (int g = 0; g < 4; g++) {
                pg[g] = preP[((0 * 4 + g) * 2 + m) * 128 + ci]
                      + preP[((1 * 4 + g) * 2 + m) * 128 + ci]
                      + preP[((2 * 4 + g) * 2 + m) * 128 + ci]
                      + preP[((3 * 4 + g) * 2 + m) * 128 + ci]
                      + ba_r[g] + xpv[g];
            }
            float fg = sigm_f(pg[0]);
            float ig = sigm_f(pg[1]);
            float og = sigm_f(pg[2]);
            float ct = sigm_f(pg[3]);
            float cps = cpP[(0 * 2 + m) * 128 + ci] + cpP[(1 * 2 + m) * 128 + ci]
                      + cpP[(2 * 2 + m) * 128 + ci] + cpP[(3 * 2 + m) * 128 + ci] + bd_r;

            float cs1  = tanh_f(cps);
            float cadj = (c_reg - cs1) + cs1 * ti;
            float cnew = fg * cadj + ig * ct;
            float hnew = og * tanh_f(cnew);
            c_reg = cnew;

            cbuf[wb * 256 + m * 128 + ci] = cnew;
            hb[wb * 256 + m * 128 + ci]   = hnew;
            out_acc += hnew * wout_r;
        }
        __syncthreads();
    }

    // ---- out[b] = sum_s h_s @ W_out + S * b_out ----
    if (t < 256) red[gp * 128 + ci] = out_acc;
    __syncthreads();
    if (t == 0) {
        float s0 = 0.0f;
        for (int k = 0; k < 128; k++) s0 += red[k];
        out[b0] = s0 + (float)SS * bo;
    }
    if (t == 1) {
        float s1 = 0.0f;
        for (int k = 0; k < 128; k++) s1 += red[128 + k];
        out[b0 + 1] = s1 + (float)SS * bo;
    }
}

// ---------------------------------------------------------------------------
extern "C" void kernel_launch(void* const* d_in, const int* in_sizes, int n_in,
                              void* d_out, int out_size)
{
    const float* inputs = (const float*)d_in[0];
    const float* TI     = (const float*)d_in[1];
    const float* W_all  = (const float*)d_in[2];
    const float* b_all  = (const float*)d_in[3];
    const float* U_all  = (const float*)d_in[4];
    const float* b_u    = (const float*)d_in[5];
    const float* W_d    = (const float*)d_in[6];
    const float* b_d    = (const float*)d_in[7];
    const float* W_out  = (const float*)d_in[8];
    const float* b_out  = (const float*)d_in[9];
    float* out = (float*)d_out;

    xproj_kernel<<<dim3(8, 4, 256), 256>>>(inputs, U_all, b_u);

    cudaFuncSetAttribute(scan_kernel,
                         cudaFuncAttributeMaxDynamicSharedMemorySize, SMEM_BYTES);
    scan_kernel<<<128, 1024, SMEM_BYTES>>>(TI, W_all, b_all, W_d, b_d,
                                           W_out, b_out, out);
}